// round 8
// baseline (speedup 1.0000x reference)
#include <cuda_runtime.h>
#include <cuda_fp16.h>
#include <cstdint>

#define NMAX 100000
#define EMAX 800000
#define HID 64

// ---------------- scratch (device globals) ----------------
__device__ float g_h0[NMAX * HID];          // fc output (fp32)
__device__ float g_h1[NMAX * HID];          // layer-1 output (fp32)
__device__ __half g_msg1[NMAX * HID];       // layer-1 messages h0@w1 (UNscaled, fp16)
__device__ __half g_msg2[NMAX * HID];       // layer-2 messages (h1@w2)*norm_out (fp16)
__device__ int   g_deg_out[NMAX];
__device__ int   g_deg_in[NMAX];
__device__ float g_norm_out[NMAX];
__device__ float g_norm_in[NMAX];
__device__ int   g_rowstart[NMAX];
__device__ int   g_cursor[NMAX];
__device__ int   g_csr_src[EMAX];
__device__ int   g_total;
__device__ float g_stats[2 * HID];

__device__ __forceinline__ float scale_const() { return 0.70710678118654752440f; }

__device__ __forceinline__ unsigned int f2tf32(float f) {
    unsigned int u;
    asm("cvt.rna.tf32.f32 %0, %1;" : "=r"(u) : "f"(f));
    return u;
}
__device__ __forceinline__ float tf32f(float f) { return __uint_as_float(f2tf32(f)); }

__device__ __forceinline__ void mma_tf32(float* d,
                                         unsigned int a0, unsigned int a1,
                                         unsigned int a2, unsigned int a3,
                                         unsigned int b0, unsigned int b1) {
    asm volatile("mma.sync.aligned.m16n8k8.row.col.f32.tf32.tf32.f32 "
                 "{%0,%1,%2,%3}, {%4,%5,%6,%7}, {%8,%9}, {%0,%1,%2,%3};"
                 : "+f"(d[0]), "+f"(d[1]), "+f"(d[2]), "+f"(d[3])
                 : "r"(a0), "r"(a1), "r"(a2), "r"(a3), "r"(b0), "r"(b1));
}

// One K=64 warp-tile MMA pass: acc[n][.] += A[row0.., k] * B[k, n*8..]
// sA: [128][68] row-major tf32 bits; sWT: [64(n)][68(k)] tf32 bits.
__device__ __forceinline__ void mma_k64(const float (*sA)[68], const float (*sWT)[68],
                                        int row0, int grp, int tig, float acc[8][4]) {
    #pragma unroll
    for (int ks = 0; ks < 8; ks++) {
        unsigned int a0 = __float_as_uint(sA[row0][ks * 8 + tig]);
        unsigned int a1 = __float_as_uint(sA[row0 + 8][ks * 8 + tig]);
        unsigned int a2 = __float_as_uint(sA[row0][ks * 8 + tig + 4]);
        unsigned int a3 = __float_as_uint(sA[row0 + 8][ks * 8 + tig + 4]);
        #pragma unroll
        for (int n = 0; n < 8; n++) {
            unsigned int b0 = __float_as_uint(sWT[n * 8 + grp][ks * 8 + tig]);
            unsigned int b1 = __float_as_uint(sWT[n * 8 + grp][ks * 8 + tig + 4]);
            mma_tf32(acc[n], a0, a1, a2, a3, b0, b1);
        }
    }
}

__device__ __forceinline__ void unpack_half4(uint2 u, float2& f0, float2& f1) {
    __half2 h0 = *reinterpret_cast<__half2*>(&u.x);
    __half2 h1 = *reinterpret_cast<__half2*>(&u.y);
    f0 = __half22float2(h0);
    f1 = __half22float2(h1);
}

// ---------------- graph build chain (side stream) ----------------
__global__ void zero_all_kernel(int n_nodes) {
    int idx = blockIdx.x * blockDim.x + threadIdx.x;
    if (idx < n_nodes) { g_deg_out[idx] = 0; g_deg_in[idx] = 0; }
    if (idx < 2 * HID) g_stats[idx] = 0.f;
    if (idx == 0) g_total = 0;
}

__global__ void degree_kernel(const int* __restrict__ src, const int* __restrict__ dst, int n_edges) {
    int e = blockIdx.x * blockDim.x + threadIdx.x;
    if (e < n_edges) {
        atomicAdd(&g_deg_out[src[e]], 1);
        atomicAdd(&g_deg_in[dst[e]], 1);
    }
}

__global__ void finalize_kernel(int n_nodes) {
    int n = blockIdx.x * blockDim.x + threadIdx.x;
    if (n < n_nodes) {
        int deg = g_deg_in[n];
        int start = atomicAdd(&g_total, deg);
        g_rowstart[n] = start;
        g_cursor[n] = start;
        int dov = g_deg_out[n]; if (dov < 1) dov = 1;
        int din = deg; if (din < 1) din = 1;
        g_norm_out[n] = rsqrtf((float)dov);
        g_norm_in[n]  = rsqrtf((float)din);
    }
}

__global__ void bin_kernel(const int* __restrict__ src, const int* __restrict__ dst, int n_edges) {
    int e = blockIdx.x * blockDim.x + threadIdx.x;
    if (e < n_edges) {
        int p = atomicAdd(&g_cursor[dst[e]], 1);
        g_csr_src[p] = src[e];
    }
}

// ======================================================================
// Fused fc + gemm1, tf32 tensor cores:
//   h0 = x @ fc_w + fc_b   -> g_h0 (fp32)
//   msg1 = h0 @ w1         -> g_msg1 (fp16)
// ======================================================================
__global__ __launch_bounds__(256) void fcg1_kernel(const float* __restrict__ x,
                                                   const float* __restrict__ fcw,
                                                   const float* __restrict__ fcb,
                                                   const float* __restrict__ w1,
                                                   int n_nodes) {
    __shared__ float sA[128][68];
    __shared__ float sWT[64][68];
    int br = blockIdx.x * 128;
    int tid = threadIdx.x;
    int warp = tid >> 5, lane = tid & 31;
    int grp = lane >> 2, tig = lane & 3;
    int row0 = warp * 16 + grp;

    float acc[8][4];
    #pragma unroll
    for (int n = 0; n < 8; n++)
        #pragma unroll
        for (int i = 0; i < 4; i++) acc[n][i] = 0.f;

    // ---- fc: K=128 in two chunks of 64 ----
    for (int kc = 0; kc < 2; kc++) {
        if (kc) __syncthreads();
        // weights transposed: sWT[n][k] = tf32(fcw[(kc*64+k)*64+n])
        for (int i = tid; i < 4096; i += 256) {
            int k = i >> 6, n = i & 63;
            sWT[n][k] = tf32f(fcw[(kc * 64 + k) * 64 + n]);
        }
        // x tile: sA[r][k] = tf32(x[row][kc*64+k])
        for (int i = tid; i < 2048; i += 256) {
            int r = i >> 4, c4 = i & 15;
            int row = br + r;
            float4 v = make_float4(0.f, 0.f, 0.f, 0.f);
            if (row < n_nodes) v = *(const float4*)&x[row * 128 + kc * 64 + (c4 << 2)];
            float4 o = make_float4(tf32f(v.x), tf32f(v.y), tf32f(v.z), tf32f(v.w));
            *(float4*)&sA[r][c4 << 2] = o;
        }
        __syncthreads();
        mma_k64(sA, sWT, row0, grp, tig, acc);
    }

    // ---- fc epilogue: +bias -> g_h0 (fp32), sA <- tf32(h0) ----
    __syncthreads();
    #pragma unroll
    for (int n = 0; n < 8; n++) {
        float2 bv = *(const float2*)&fcb[n * 8 + tig * 2];
        float h00 = acc[n][0] + bv.x, h01 = acc[n][1] + bv.y;
        float h10 = acc[n][2] + bv.x, h11 = acc[n][3] + bv.y;
        int ra = br + row0, rb = br + row0 + 8;
        if (ra < n_nodes) *(float2*)&g_h0[ra * 64 + n * 8 + tig * 2] = make_float2(h00, h01);
        if (rb < n_nodes) *(float2*)&g_h0[rb * 64 + n * 8 + tig * 2] = make_float2(h10, h11);
        *(float2*)&sA[row0][n * 8 + tig * 2]     = make_float2(tf32f(h00), tf32f(h01));
        *(float2*)&sA[row0 + 8][n * 8 + tig * 2] = make_float2(tf32f(h10), tf32f(h11));
        acc[n][0] = 0.f; acc[n][1] = 0.f; acc[n][2] = 0.f; acc[n][3] = 0.f;
    }
    // w1 transposed
    for (int i = tid; i < 4096; i += 256) {
        int k = i >> 6, n = i & 63;
        sWT[n][k] = tf32f(w1[k * 64 + n]);
    }
    __syncthreads();

    // ---- gemm1 ----
    mma_k64(sA, sWT, row0, grp, tig, acc);

    // msg1 epilogue (fp16, unscaled)
    int ra = br + row0, rb = br + row0 + 8;
    #pragma unroll
    for (int n = 0; n < 8; n++) {
        if (ra < n_nodes) {
            __half2 p = __floats2half2_rn(acc[n][0], acc[n][1]);
            *reinterpret_cast<__half2*>(&g_msg1[ra * 64 + n * 8 + tig * 2]) = p;
        }
        if (rb < n_nodes) {
            __half2 p = __floats2half2_rn(acc[n][2], acc[n][3]);
            *reinterpret_cast<__half2*>(&g_msg1[rb * 64 + n * 8 + tig * 2]) = p;
        }
    }
}

// ======================================================================
// Fused CSR-gather + layer-1 epilogue + gemm2 (tf32):
//   agg = norm_in * sum msg1[s]*norm_out[s]
//   h1  = (h0 + agg + b1)*SCALE     -> g_h1 (fp32), sA <- tf32(h1)
//   msg2 = (h1 @ w2) * norm_out     -> g_msg2 (fp16, pre-scaled)
// ======================================================================
__global__ __launch_bounds__(256) void gemm2_fused_kernel(const float* __restrict__ b1,
                                                          const float* __restrict__ w2,
                                                          int n_nodes) {
    __shared__ float sA[128][68];
    __shared__ float sWT[64][68];
    int br = blockIdx.x * 128;
    int tid = threadIdx.x;
    int warp = tid >> 5, lane = tid & 31;
    int grp = lane >> 2, tig = lane & 3;
    int row0 = warp * 16 + grp;
    int lc4 = tid & 15, lr0 = tid >> 4;
    const float sc = scale_const();
    const uint2* __restrict__ m1 = reinterpret_cast<const uint2*>(g_msg1);

    // w2 transposed into sWT
    for (int i = tid; i < 4096; i += 256) {
        int k = i >> 6, n = i & 63;
        sWT[n][k] = tf32f(w2[k * 64 + n]);
    }

    // gather + layer-1 epilogue -> g_h1 (fp32), sA (tf32)
    {
        float4 bv = *(const float4*)&b1[lc4 << 2];
        #pragma unroll
        for (int t = 0; t < 8; t++) {
            int r = lr0 + t * 16;
            int row = br + r;
            float4 v = make_float4(0.f, 0.f, 0.f, 0.f);
            if (row < n_nodes) {
                int beg = g_rowstart[row];
                int end = beg + g_deg_in[row];
                float4 a0 = make_float4(0.f, 0.f, 0.f, 0.f);
                float4 a1 = make_float4(0.f, 0.f, 0.f, 0.f);
                int e = beg;
                for (; e + 4 <= end; e += 4) {
                    int s0 = g_csr_src[e], s1 = g_csr_src[e + 1];
                    int s2 = g_csr_src[e + 2], s3 = g_csr_src[e + 3];
                    float n0 = g_norm_out[s0], n1 = g_norm_out[s1];
                    float n2 = g_norm_out[s2], n3 = g_norm_out[s3];
                    uint2 u0 = m1[s0 * 16 + lc4];
                    uint2 u1 = m1[s1 * 16 + lc4];
                    uint2 u2 = m1[s2 * 16 + lc4];
                    uint2 u3 = m1[s3 * 16 + lc4];
                    float2 p, q;
                    unpack_half4(u0, p, q);
                    a0.x = fmaf(p.x, n0, a0.x); a0.y = fmaf(p.y, n0, a0.y);
                    a0.z = fmaf(q.x, n0, a0.z); a0.w = fmaf(q.y, n0, a0.w);
                    unpack_half4(u1, p, q);
                    a1.x = fmaf(p.x, n1, a1.x); a1.y = fmaf(p.y, n1, a1.y);
                    a1.z = fmaf(q.x, n1, a1.z); a1.w = fmaf(q.y, n1, a1.w);
                    unpack_half4(u2, p, q);
                    a0.x = fmaf(p.x, n2, a0.x); a0.y = fmaf(p.y, n2, a0.y);
                    a0.z = fmaf(q.x, n2, a0.z); a0.w = fmaf(q.y, n2, a0.w);
                    unpack_half4(u3, p, q);
                    a1.x = fmaf(p.x, n3, a1.x); a1.y = fmaf(p.y, n3, a1.y);
                    a1.z = fmaf(q.x, n3, a1.z); a1.w = fmaf(q.y, n3, a1.w);
                }
                for (; e < end; e++) {
                    int s = g_csr_src[e];
                    float ns = g_norm_out[s];
                    float2 p, q;
                    unpack_half4(m1[s * 16 + lc4], p, q);
                    a0.x = fmaf(p.x, ns, a0.x); a0.y = fmaf(p.y, ns, a0.y);
                    a0.z = fmaf(q.x, ns, a0.z); a0.w = fmaf(q.y, ns, a0.w);
                }
                float ni = g_norm_in[row];
                float4 h0v = *(const float4*)&g_h0[row * 64 + (lc4 << 2)];
                v.x = (h0v.x + (a0.x + a1.x) * ni + bv.x) * sc;
                v.y = (h0v.y + (a0.y + a1.y) * ni + bv.y) * sc;
                v.z = (h0v.z + (a0.z + a1.z) * ni + bv.z) * sc;
                v.w = (h0v.w + (a0.w + a1.w) * ni + bv.w) * sc;
                *(float4*)&g_h1[row * 64 + (lc4 << 2)] = v;
            }
            float4 o = make_float4(tf32f(v.x), tf32f(v.y), tf32f(v.z), tf32f(v.w));
            *(float4*)&sA[r][lc4 << 2] = o;
        }
    }
    __syncthreads();

    float acc[8][4];
    #pragma unroll
    for (int n = 0; n < 8; n++)
        #pragma unroll
        for (int i = 0; i < 4; i++) acc[n][i] = 0.f;

    mma_k64(sA, sWT, row0, grp, tig, acc);

    // msg2 epilogue: scale by norm_out, pack fp16
    int ra = br + row0, rb = br + row0 + 8;
    float na = (ra < n_nodes) ? g_norm_out[ra] : 0.f;
    float nb = (rb < n_nodes) ? g_norm_out[rb] : 0.f;
    #pragma unroll
    for (int n = 0; n < 8; n++) {
        if (ra < n_nodes) {
            __half2 p = __floats2half2_rn(acc[n][0] * na, acc[n][1] * na);
            *reinterpret_cast<__half2*>(&g_msg2[ra * 64 + n * 8 + tig * 2]) = p;
        }
        if (rb < n_nodes) {
            __half2 p = __floats2half2_rn(acc[n][2] * nb, acc[n][3] * nb);
            *reinterpret_cast<__half2*>(&g_msg2[rb * 64 + n * 8 + tig * 2]) = p;
        }
    }
}

// ---------------- fused layer-2 aggregation + epilogue + BN stats ----------------
__global__ __launch_bounds__(256) void agg2_stats_kernel(const float* __restrict__ b2,
                                                         float* __restrict__ out,
                                                         int n_nodes) {
    __shared__ float ssum[64], ssq[64];
    if (threadIdx.x < 64) { ssum[threadIdx.x] = 0.f; ssq[threadIdx.x] = 0.f; }
    __syncthreads();
    int c = threadIdx.x & 15;
    float4 bv = reinterpret_cast<const float4*>(b2)[c];
    const float sc = scale_const();
    float4 ls = make_float4(0.f, 0.f, 0.f, 0.f);
    float4 lq = make_float4(0.f, 0.f, 0.f, 0.f);
    const uint2* __restrict__ m2 = reinterpret_cast<const uint2*>(g_msg2);

    for (int node = blockIdx.x * 16 + (threadIdx.x >> 4); node < n_nodes; node += gridDim.x * 16) {
        int beg = g_rowstart[node];
        int end = beg + g_deg_in[node];
        float4 a0 = make_float4(0.f, 0.f, 0.f, 0.f);
        float4 a1 = make_float4(0.f, 0.f, 0.f, 0.f);
        int e = beg;
        for (; e + 4 <= end; e += 4) {
            int s0 = g_csr_src[e], s1 = g_csr_src[e + 1];
            int s2 = g_csr_src[e + 2], s3 = g_csr_src[e + 3];
            uint2 u0 = m2[s0 * 16 + c];
            uint2 u1 = m2[s1 * 16 + c];
            uint2 u2 = m2[s2 * 16 + c];
            uint2 u3 = m2[s3 * 16 + c];
            float2 p, q;
            unpack_half4(u0, p, q);
            a0.x += p.x; a0.y += p.y; a0.z += q.x; a0.w += q.y;
            unpack_half4(u1, p, q);
            a1.x += p.x; a1.y += p.y; a1.z += q.x; a1.w += q.y;
            unpack_half4(u2, p, q);
            a0.x += p.x; a0.y += p.y; a0.z += q.x; a0.w += q.y;
            unpack_half4(u3, p, q);
            a1.x += p.x; a1.y += p.y; a1.z += q.x; a1.w += q.y;
        }
        for (; e < end; e++) {
            int s = g_csr_src[e];
            float2 p, q;
            unpack_half4(m2[s * 16 + c], p, q);
            a0.x += p.x; a0.y += p.y; a0.z += q.x; a0.w += q.y;
        }
        float ni = g_norm_in[node];
        float4 h1v = reinterpret_cast<const float4*>(g_h1)[node * 16 + c];
        float4 h2;
        h2.x = (h1v.x + (a0.x + a1.x) * ni + bv.x) * sc;
        h2.y = (h1v.y + (a0.y + a1.y) * ni + bv.y) * sc;
        h2.z = (h1v.z + (a0.z + a1.z) * ni + bv.z) * sc;
        h2.w = (h1v.w + (a0.w + a1.w) * ni + bv.w) * sc;
        reinterpret_cast<float4*>(out)[node * 16 + c] = h2;
        ls.x += h2.x; ls.y += h2.y; ls.z += h2.z; ls.w += h2.w;
        lq.x += h2.x * h2.x; lq.y += h2.y * h2.y; lq.z += h2.z * h2.z; lq.w += h2.w * h2.w;
    }
    atomicAdd(&ssum[c * 4 + 0], ls.x); atomicAdd(&ssq[c * 4 + 0], lq.x);
    atomicAdd(&ssum[c * 4 + 1], ls.y); atomicAdd(&ssq[c * 4 + 1], lq.y);
    atomicAdd(&ssum[c * 4 + 2], ls.z); atomicAdd(&ssq[c * 4 + 2], lq.z);
    atomicAdd(&ssum[c * 4 + 3], ls.w); atomicAdd(&ssq[c * 4 + 3], lq.w);
    __syncthreads();
    if (threadIdx.x < 64) {
        atomicAdd(&g_stats[threadIdx.x], ssum[threadIdx.x]);
        atomicAdd(&g_stats[64 + threadIdx.x], ssq[threadIdx.x]);
    }
}

// ---------------- BN apply ----------------
__global__ __launch_bounds__(256) void bn_kernel(float* __restrict__ out,
                                                 const float* __restrict__ gamma,
                                                 const float* __restrict__ beta,
                                                 int n_nodes) {
    __shared__ float s_scale[64], s_shift[64];
    if (threadIdx.x < 64) {
        int j = threadIdx.x;
        float inv_n = 1.f / (float)n_nodes;
        float mu = g_stats[j] * inv_n;
        float var = g_stats[64 + j] * inv_n - mu * mu;
        if (var < 0.f) var = 0.f;
        float g = rsqrtf(var + 1e-5f) * gamma[j];
        s_scale[j] = g;
        s_shift[j] = beta[j] - mu * g;
    }
    __syncthreads();
    int total4 = n_nodes * 16;
    int stride = gridDim.x * blockDim.x;
    for (int i = blockIdx.x * blockDim.x + threadIdx.x; i < total4; i += stride) {
        float4 v = reinterpret_cast<float4*>(out)[i];
        int j0 = (i & 15) << 2;
        v.x = v.x * s_scale[j0 + 0] + s_shift[j0 + 0];
        v.y = v.y * s_scale[j0 + 1] + s_shift[j0 + 1];
        v.z = v.z * s_scale[j0 + 2] + s_shift[j0 + 2];
        v.w = v.w * s_scale[j0 + 3] + s_shift[j0 + 3];
        reinterpret_cast<float4*>(out)[i] = v;
    }
}

// ---------------- launch (graph build forked onto a side stream) ----------------
extern "C" void kernel_launch(void* const* d_in, const int* in_sizes, int n_in,
                              void* d_out, int out_size) {
    const int*   src   = (const int*)d_in[0];
    const int*   dst   = (const int*)d_in[1];
    const float* x     = (const float*)d_in[2];
    const float* fc_w  = (const float*)d_in[3];
    const float* fc_b  = (const float*)d_in[4];
    const float* w1    = (const float*)d_in[5];
    const float* b1    = (const float*)d_in[6];
    const float* w2    = (const float*)d_in[7];
    const float* b2    = (const float*)d_in[8];
    const float* gamma = (const float*)d_in[9];
    const float* beta  = (const float*)d_in[10];
    float* out = (float*)d_out;

    int n_edges = in_sizes[0];
    int n_nodes = in_sizes[2] / 128;

    static cudaStream_t s_build = nullptr;
    static cudaEvent_t ev_fork = nullptr, ev_join = nullptr;
    if (s_build == nullptr) {
        cudaStreamCreateWithFlags(&s_build, cudaStreamNonBlocking);
        cudaEventCreateWithFlags(&ev_fork, cudaEventDisableTiming);
        cudaEventCreateWithFlags(&ev_join, cudaEventDisableTiming);
    }

    cudaEventRecord(ev_fork, 0);
    cudaStreamWaitEvent(s_build, ev_fork, 0);
    zero_all_kernel<<<(n_nodes + 255) / 256, 256, 0, s_build>>>(n_nodes);
    degree_kernel<<<(n_edges + 255) / 256, 256, 0, s_build>>>(src, dst, n_edges);
    finalize_kernel<<<(n_nodes + 255) / 256, 256, 0, s_build>>>(n_nodes);
    bin_kernel<<<(n_edges + 255) / 256, 256, 0, s_build>>>(src, dst, n_edges);
    cudaEventRecord(ev_join, s_build);

    int gblocks = (n_nodes + 127) / 128;
    fcg1_kernel<<<gblocks, 256>>>(x, fc_w, fc_b, w1, n_nodes);

    cudaStreamWaitEvent(0, ev_join, 0);
    gemm2_fused_kernel<<<gblocks, 256>>>(b1, w2, n_nodes);
    agg2_stats_kernel<<<1184, 256>>>(b2, out, n_nodes);
    bn_kernel<<<512, 256>>>(out, gamma, beta, n_nodes);
}